// round 3
// baseline (speedup 1.0000x reference)
#include <cuda_runtime.h>
#include <math.h>
#include <stdint.h>

typedef unsigned long long ull;

#define NB     128     // batches = nspin*nk*ni = 2*4*16
#define NG     8000    // plane waves = 20^3
#define NPTS   8000    // real-space points = 20^3
#define NGR    20      // grid per dim
#define TP     32      // points per CTA
#define NT     256     // threads per CTA
#define NCHUNK 400     // NG / NGR

__device__ float d_B[9];      // B = 2*pi * inv(A)^T, row-major
__device__ float d_scale;     // 1/sqrt(|det A|)

__global__ void setup_kernel(const float* __restrict__ A) {
    if (threadIdx.x == 0) {
        double a00=A[0],a01=A[1],a02=A[2];
        double a10=A[3],a11=A[4],a12=A[5];
        double a20=A[6],a21=A[7],a22=A[8];
        double c00 =  (a11*a22 - a12*a21);
        double c01 = -(a10*a22 - a12*a20);
        double c02 =  (a10*a21 - a11*a20);
        double c10 = -(a01*a22 - a02*a21);
        double c11 =  (a00*a22 - a02*a20);
        double c12 = -(a00*a21 - a01*a20);
        double c20 =  (a01*a12 - a02*a11);
        double c21 = -(a00*a12 - a02*a10);
        double c22 =  (a00*a11 - a01*a10);
        double det = a00*c00 + a01*c01 + a02*c02;
        double tp  = 6.283185307179586476925286766559;
        double s   = tp / det;   // B[i][j] = 2pi * cof[i][j] / det
        d_B[0]=(float)(c00*s); d_B[1]=(float)(c01*s); d_B[2]=(float)(c02*s);
        d_B[3]=(float)(c10*s); d_B[4]=(float)(c11*s); d_B[5]=(float)(c12*s);
        d_B[6]=(float)(c20*s); d_B[7]=(float)(c21*s); d_B[8]=(float)(c22*s);
        d_scale = (float)(1.0 / sqrt(fabs(det)));
    }
}

__device__ __forceinline__ ull pack2(float lo, float hi) {
    ull r;
    asm("mov.b64 %0, {%1, %2};" : "=l"(r) : "f"(lo), "f"(hi));
    return r;
}
__device__ __forceinline__ float2 unpack2(ull v) {
    float lo, hi;
    asm("mov.b64 {%0, %1}, %2;" : "=f"(lo), "=f"(hi) : "l"(v));
    return make_float2(lo, hi);
}
__device__ __forceinline__ ull fma2(ull a, ull b, ull c) {
    ull d;
    asm("fma.rn.f32x2 %0, %1, %2, %3;" : "=l"(d) : "l"(a), "l"(b), "l"(c));
    return d;
}
__device__ __forceinline__ float2 cmul(float2 a, float2 b) {
    return make_float2(a.x*b.x - a.y*b.y, a.x*b.y + a.y*b.x);
}

// Thread map: tb = lane (0..31) -> batches b = tb + 32j (j=0..3)
//             tw = warp (0..7)  -> 4 local points tw*4 .. tw*4+3 (2 f32x2 pairs)
// c-chunk loads: thread t -> row b = t>>1, half h = t&1 -> 10 g's
__global__ void __launch_bounds__(NT, 2) bloch_kernel(
    const float* __restrict__ cre, const float* __restrict__ cim,
    const float* __restrict__ r,   const float* __restrict__ kg,
    float* __restrict__ out, int out_elems)
{
    __shared__ float2 se[3][TP][NGR];      // e^{i m u_d} tables  (15.0 KB)
    __shared__ float2 sc[NGR][NB];         // c chunk, XOR-swizzled (20 KB)
    __shared__ float2 spr[NGR][TP/2];      // Re(phase) point-pairs (2.5 KB)
    __shared__ float2 spi[NGR][TP/2];      // Im(phase) point-pairs (2.5 KB)

    const int tid   = threadIdx.x;
    const int tb    = tid & 31;
    const int tw    = tid >> 5;
    const int pbase = blockIdx.x * TP;

    // ---- e tables: e_d[p][i] = exp(i * m(i) * (B_d . r_p)) ----
    for (int t = tid; t < 3 * TP * NGR; t += NT) {
        int d   = t / (TP * NGR);
        int rem = t - d * TP * NGR;
        int p   = rem / NGR;
        int i   = rem - p * NGR;
        int m   = (i < NGR/2) ? i : i - NGR;   // fftfreq(20)*20
        const float* rp = r + (pbase + p) * 3;
        float u = d_B[3*d+0]*rp[0] + d_B[3*d+1]*rp[1] + d_B[3*d+2]*rp[2];
        float sv, cv;
        sincosf((float)m * u, &sv, &cv);
        se[d][p][i] = make_float2(cv, sv);
    }

    // ---- accumulators: U = sum c*Re(ph), V = sum c*Im(ph), point-pair packed ----
    ull Ur[2][4], Ui[2][4], Vr[2][4], Vi[2][4];
    #pragma unroll
    for (int pp = 0; pp < 2; pp++)
        #pragma unroll
        for (int j = 0; j < 4; j++) { Ur[pp][j]=0ull; Ui[pp][j]=0ull; Vr[pp][j]=0ull; Vi[pp][j]=0ull; }

    // ---- coefficient prefetch: thread t owns row b=t>>1, g-half h=t&1 ----
    const int ldrow  = tid >> 1;          // 0..127
    const int ldhalf = (tid & 1) * 10;    // 0 or 10
    const float* cre_base = cre + ldrow * NG + ldhalf;
    const float* cim_base = cim + ldrow * NG + ldhalf;

    float lre[10], lim[10];
    #pragma unroll
    for (int i = 0; i < 10; i++) {
        lre[i] = cre_base[i];
        lim[i] = cim_base[i];
    }
    __syncthreads();   // e tables ready

    const int pairq = tw * 2;   // first point-pair index of this warp

    for (int c = 0; c < NCHUNK; c++) {
        // -- fill smem: c chunk, XOR-swizzled: sc[g][row^g] = c[row][c*20+g] --
        #pragma unroll
        for (int i = 0; i < 10; i++) {
            int gl = ldhalf + i;
            sc[gl][ldrow ^ gl] = make_float2(lre[i], lim[i]);
        }
        // -- phases for this chunk: ph[p][g] = e1[i1]*e2[i2]*e3[i3], (i1,i2) = c --
        {
            int i1 = c / NGR;
            int i2 = c - i1 * NGR;
            for (int t = tid; t < (TP/2) * NGR; t += NT) {   // 320 tasks
                int q  = t / NGR;
                int i3 = t - q * NGR;
                int p0 = 2*q, p1 = 2*q + 1;
                float2 pa = cmul(cmul(se[0][p0][i1], se[1][p0][i2]), se[2][p0][i3]);
                float2 pb = cmul(cmul(se[0][p1][i1], se[1][p1][i2]), se[2][p1][i3]);
                spr[i3][q] = make_float2(pa.x, pb.x);
                spi[i3][q] = make_float2(pa.y, pb.y);
            }
        }
        __syncthreads();

        // -- prefetch next chunk into registers (overlaps with FMA below) --
        if (c + 1 < NCHUNK) {
            const float* cr = cre_base + (c + 1) * NGR;
            const float* ci = cim_base + (c + 1) * NGR;
            #pragma unroll
            for (int i = 0; i < 10; i++) {
                lre[i] = cr[i];
                lim[i] = ci[i];
            }
        }

        // -- main FMA loop over the 20 g's of this chunk --
        #pragma unroll 4
        for (int g = 0; g < NGR; g++) {
            ull pr0 = *(const ull*)&spr[g][pairq];
            ull pr1 = *(const ull*)&spr[g][pairq + 1];
            ull pi0 = *(const ull*)&spi[g][pairq];
            ull pi1 = *(const ull*)&spi[g][pairq + 1];
            int tbx = tb ^ g;
            #pragma unroll
            for (int j = 0; j < 4; j++) {
                float2 cv = sc[g][tbx + 32*j];
                ull crcr = pack2(cv.x, cv.x);
                ull cici = pack2(cv.y, cv.y);
                Ur[0][j] = fma2(crcr, pr0, Ur[0][j]);
                Ui[0][j] = fma2(cici, pr0, Ui[0][j]);
                Vr[0][j] = fma2(crcr, pi0, Vr[0][j]);
                Vi[0][j] = fma2(cici, pi0, Vi[0][j]);
                Ur[1][j] = fma2(crcr, pr1, Ur[1][j]);
                Ui[1][j] = fma2(cici, pr1, Ui[1][j]);
                Vr[1][j] = fma2(crcr, pi1, Vr[1][j]);
                Vi[1][j] = fma2(cici, pi1, Vi[1][j]);
            }
        }
        __syncthreads();   // before next chunk overwrites smem
    }

    // ---- epilogue: psi = (U_r - V_i) + i(U_i + V_r), * exp(i k.r) / sqrt(vol) ----
    // Output layout guarded by out_elems (floats):
    //   out_elems >= 2*NB*NPTS : interleaved (re,im) pairs, batch-major
    //   otherwise              : real part only
    const bool cplx = (out_elems >= 2 * NB * NPTS);
    const float scale = d_scale;
    #pragma unroll
    for (int pp = 0; pp < 2; pp++) {
        #pragma unroll
        for (int j = 0; j < 4; j++) {
            float2 ur = unpack2(Ur[pp][j]);
            float2 ui = unpack2(Ui[pp][j]);
            float2 vr = unpack2(Vr[pp][j]);
            float2 vi = unpack2(Vi[pp][j]);
            int b = tb + 32*j;
            int k = (b >> 4) & 3;
            float k0 = kg[3*k+0], k1 = kg[3*k+1], k2 = kg[3*k+2];
            #pragma unroll
            for (int pl = 0; pl < 2; pl++) {
                int p = pbase + tw*4 + pp*2 + pl;
                float re = (pl ? ur.y : ur.x) - (pl ? vi.y : vi.x);
                float im = (pl ? ui.y : ui.x) + (pl ? vr.y : vr.x);
                const float* rp = r + p * 3;
                float ang = k0*rp[0] + k1*rp[1] + k2*rp[2];
                float s, cc;
                sincosf(ang, &s, &cc);
                float ore = (re*cc - im*s) * scale;
                float oim = (re*s + im*cc) * scale;
                size_t idx = (size_t)b * NPTS + p;
                if (cplx) {
                    ((float2*)out)[idx] = make_float2(ore, oim);
                } else {
                    out[idx] = ore;
                }
            }
        }
    }
}

extern "C" void kernel_launch(void* const* d_in, const int* in_sizes, int n_in,
                              void* d_out, int out_size) {
    // Resolve inputs by size, accepting either ELEMENT counts or BYTE counts:
    //   A: 9 | 36, k_grid: 12 | 48, r: 24000 | 96000, cg: 1024000 | 4096000.
    // The two cg arrays are taken in order of appearance as (cg_real, cg_imag)
    // (setup_inputs dict insertion order). Positional fallback if unmatched.
    const float* A   = nullptr;
    const float* kg  = nullptr;
    const float* r   = nullptr;
    const float* cre = nullptr;
    const float* cim = nullptr;
    for (int i = 0; i < n_in; i++) {
        const float* p = (const float*)d_in[i];
        long long sz = in_sizes[i];
        if (sz == 9 || sz == 36)               A = p;
        else if (sz == 12 || sz == 48)         kg = p;
        else if (sz == 24000 || sz == 96000)   r = p;
        else if (sz == (long long)NB * NG || sz == (long long)NB * NG * 4) {
            if (!cre) cre = p; else cim = p;
        }
    }
    if (!A || !kg || !r || !cre || !cim) {
        // Fallback: dict insertion order A, k_grid, cg_real, cg_imag, r
        if (n_in >= 5) {
            A   = (const float*)d_in[0];
            kg  = (const float*)d_in[1];
            cre = (const float*)d_in[2];
            cim = (const float*)d_in[3];
            r   = (const float*)d_in[4];
        } else {
            return;  // cannot resolve; do nothing rather than crash
        }
    }

    setup_kernel<<<1, 32>>>(A);
    bloch_kernel<<<NPTS / TP, NT>>>(cre, cim, r, kg, (float*)d_out, out_size);
}

// round 6
// speedup vs baseline: 1.3332x; 1.3332x over previous
#include <cuda_runtime.h>
#include <math.h>
#include <stdint.h>

typedef unsigned long long ull;

#define NB     128     // batches = nspin*nk*ni = 2*4*16
#define NG     8000    // plane waves = 20^3
#define NPTS   8000    // real-space points = 20^3
#define NGR    20      // grid per dim
#define TP     32      // points per CTA
#define NT     128     // threads per CTA (4 warps)
#define NPAIR  16      // point-pairs per CTA (4 warps x 4 pairs)
#define NCHUNK 400     // NG / NGR

__device__ float d_B[9];      // B = 2*pi * inv(A)^T, row-major
__device__ float d_scale;     // 1/sqrt(|det A|)

__global__ void setup_kernel(const float* __restrict__ A) {
    if (threadIdx.x == 0) {
        double a00=A[0],a01=A[1],a02=A[2];
        double a10=A[3],a11=A[4],a12=A[5];
        double a20=A[6],a21=A[7],a22=A[8];
        double c00 =  (a11*a22 - a12*a21);
        double c01 = -(a10*a22 - a12*a20);
        double c02 =  (a10*a21 - a11*a20);
        double c10 = -(a01*a22 - a02*a21);
        double c11 =  (a00*a22 - a02*a20);
        double c12 = -(a00*a21 - a01*a20);
        double c20 =  (a01*a12 - a02*a11);
        double c21 = -(a00*a12 - a02*a10);
        double c22 =  (a00*a11 - a01*a10);
        double det = a00*c00 + a01*c01 + a02*c02;
        double tp  = 6.283185307179586476925286766559;
        double s   = tp / det;
        d_B[0]=(float)(c00*s); d_B[1]=(float)(c01*s); d_B[2]=(float)(c02*s);
        d_B[3]=(float)(c10*s); d_B[4]=(float)(c11*s); d_B[5]=(float)(c12*s);
        d_B[6]=(float)(c20*s); d_B[7]=(float)(c21*s); d_B[8]=(float)(c22*s);
        d_scale = (float)(1.0 / sqrt(fabs(det)));
    }
}

__device__ __forceinline__ ull pack2(float lo, float hi) {
    ull r;
    asm("mov.b64 %0, {%1, %2};" : "=l"(r) : "f"(lo), "f"(hi));
    return r;
}
__device__ __forceinline__ float2 unpack2(ull v) {
    float lo, hi;
    asm("mov.b64 {%0, %1}, %2;" : "=f"(lo), "=f"(hi) : "l"(v));
    return make_float2(lo, hi);
}
__device__ __forceinline__ ull fma2(ull a, ull b, ull c) {
    ull d;
    asm("fma.rn.f32x2 %0, %1, %2, %3;" : "=l"(d) : "l"(a), "l"(b), "l"(c));
    return d;
}
__device__ __forceinline__ float2 cmul(float2 a, float2 b) {
    return make_float2(a.x*b.x - a.y*b.y, a.x*b.y + a.y*b.x);
}

// Thread map: tb = lane (0..31) -> batches b = tb + 32j (j=0..3)
//             tw = warp (0..3)  -> 4 point-pairs q = tw*4..tw*4+3 (8 points)
// Coefficient loads: thread t owns full batch row b = t (20 g's via 5x float4)
__global__ void __launch_bounds__(NT, 2) bloch_kernel(
    const float* __restrict__ cre, const float* __restrict__ cim,
    const float* __restrict__ r,   const float* __restrict__ kg,
    float* __restrict__ out, int out_elems)
{
    __shared__ float2 se[3][TP][NGR];     // e^{i m u_d} tables (15.0 KB)
    __shared__ float2 sc[NGR][NB];        // c chunk, XOR-swizzled (20 KB)
    __shared__ ull spr[NGR][NPAIR];       // packed Re(phase) pairs (2.5 KB)
    __shared__ ull spi[NGR][NPAIR];       // packed Im(phase) pairs (2.5 KB)
    __shared__ ull sps[NGR][NPAIR];       // packed Re+Im pairs     (2.5 KB)

    const int tid   = threadIdx.x;
    const int tb    = tid & 31;
    const int tw    = tid >> 5;
    const int pbase = blockIdx.x * TP;

    // ---- e tables: e_d[p][i] = exp(i * m(i) * (B_d . r_p)) ----
    for (int t = tid; t < 3 * TP * NGR; t += NT) {
        int d   = t / (TP * NGR);
        int rem = t - d * TP * NGR;
        int p   = rem / NGR;
        int i   = rem - p * NGR;
        int m   = (i < NGR/2) ? i : i - NGR;   // fftfreq(20)*20
        const float* rp = r + (pbase + p) * 3;
        float u = d_B[3*d+0]*rp[0] + d_B[3*d+1]*rp[1] + d_B[3*d+2]*rp[2];
        float sv, cv;
        sincosf((float)m * u, &sv, &cv);
        se[d][p][i] = make_float2(cv, sv);
    }

    // ---- Karatsuba accumulators, packed over point-pairs ----
    // S1 = sum cr*pr, S2 = sum ci*pi, S3 = sum (cr+ci)*(pr+pi)
    ull A1[4][4], A2[4][4], A3[4][4];
    #pragma unroll
    for (int pp = 0; pp < 4; pp++)
        #pragma unroll
        for (int j = 0; j < 4; j++) { A1[pp][j]=0ull; A2[pp][j]=0ull; A3[pp][j]=0ull; }

    // ---- coefficient prefetch: thread owns batch row b = tid, 20 g's ----
    const float4* cre4 = (const float4*)(cre + tid * NG);
    const float4* cim4 = (const float4*)(cim + tid * NG);
    float4 lre[5], lim[5];
    #pragma unroll
    for (int i = 0; i < 5; i++) { lre[i] = cre4[i]; lim[i] = cim4[i]; }
    __syncthreads();   // e tables ready

    const int pairq = tw * 4;   // first point-pair of this warp

    for (int c = 0; c < NCHUNK; c++) {
        // -- store c chunk to smem, XOR-swizzled: sc[g][b^g] = (cre,cim)[b][c*20+g] --
        #pragma unroll
        for (int i = 0; i < 5; i++) {
            int g0 = 4 * i;
            sc[g0+0][tid ^ (g0+0)] = make_float2(lre[i].x, lim[i].x);
            sc[g0+1][tid ^ (g0+1)] = make_float2(lre[i].y, lim[i].y);
            sc[g0+2][tid ^ (g0+2)] = make_float2(lre[i].z, lim[i].z);
            sc[g0+3][tid ^ (g0+3)] = make_float2(lre[i].w, lim[i].w);
        }
        // -- phases: ph[p][g] = e1[i1]*e2[i2]*e3[i3], (i1,i2) fixed by chunk --
        {
            int i1 = c / NGR;
            int i2 = c - i1 * NGR;
            for (int t = tid; t < NPAIR * NGR; t += NT) {   // 320 tasks
                int q  = t / NGR;
                int i3 = t - q * NGR;
                int p0 = 2*q, p1 = 2*q + 1;
                float2 pa = cmul(cmul(se[0][p0][i1], se[1][p0][i2]), se[2][p0][i3]);
                float2 pb = cmul(cmul(se[0][p1][i1], se[1][p1][i2]), se[2][p1][i3]);
                spr[i3][q] = pack2(pa.x, pb.x);
                spi[i3][q] = pack2(pa.y, pb.y);
                sps[i3][q] = pack2(pa.x + pa.y, pb.x + pb.y);
            }
        }
        __syncthreads();

        // -- prefetch next chunk (overlaps the FMA loop) --
        if (c + 1 < NCHUNK) {
            int base = (c + 1) * 5;
            #pragma unroll
            for (int i = 0; i < 5; i++) { lre[i] = cre4[base + i]; lim[i] = cim4[base + i]; }
        }

        // -- main FMA loop: 48 fma2 per g per thread --
        #pragma unroll 2
        for (int g = 0; g < NGR; g++) {
            ull pr[4], pi[4], ps[4];
            #pragma unroll
            for (int q = 0; q < 4; q++) {
                pr[q] = spr[g][pairq+q];
                pi[q] = spi[g][pairq+q];
                ps[q] = sps[g][pairq+q];
            }
            int tbx = tb ^ g;
            #pragma unroll
            for (int j = 0; j < 4; j++) {
                float2 cv = sc[g][tbx + 32*j];
                ull crcr = pack2(cv.x, cv.x);
                #pragma unroll
                for (int q = 0; q < 4; q++) A1[q][j] = fma2(crcr, pr[q], A1[q][j]);
                ull cici = pack2(cv.y, cv.y);
                #pragma unroll
                for (int q = 0; q < 4; q++) A2[q][j] = fma2(cici, pi[q], A2[q][j]);
                float cs = cv.x + cv.y;
                ull cscs = pack2(cs, cs);
                #pragma unroll
                for (int q = 0; q < 4; q++) A3[q][j] = fma2(cscs, ps[q], A3[q][j]);
            }
        }
        __syncthreads();   // before next chunk overwrites smem
    }

    // ---- epilogue: Re = S1 - S2, Im = S3 - S1 - S2; * exp(i k.r) / sqrt(vol) ----
    const bool cplx = (out_elems >= 2 * NB * NPTS);
    const float scale = d_scale;
    #pragma unroll
    for (int pp = 0; pp < 4; pp++) {
        #pragma unroll
        for (int j = 0; j < 4; j++) {
            float2 s1 = unpack2(A1[pp][j]);
            float2 s2 = unpack2(A2[pp][j]);
            float2 s3 = unpack2(A3[pp][j]);
            int b = tb + 32*j;
            int k = (b >> 4) & 3;
            float k0 = kg[3*k+0], k1 = kg[3*k+1], k2 = kg[3*k+2];
            #pragma unroll
            for (int pl = 0; pl < 2; pl++) {
                int p = pbase + 2*(pairq + pp) + pl;
                float re = (pl ? s1.y : s1.x) - (pl ? s2.y : s2.x);
                float im = (pl ? s3.y : s3.x) - (pl ? s1.y : s1.x) - (pl ? s2.y : s2.x);
                const float* rp = r + p * 3;
                float ang = k0*rp[0] + k1*rp[1] + k2*rp[2];
                float s, cc;
                sincosf(ang, &s, &cc);
                float ore = (re*cc - im*s) * scale;
                float oim = (re*s + im*cc) * scale;
                size_t idx = (size_t)b * NPTS + p;
                if (cplx) {
                    ((float2*)out)[idx] = make_float2(ore, oim);
                } else {
                    out[idx] = ore;
                }
            }
        }
    }
}

extern "C" void kernel_launch(void* const* d_in, const int* in_sizes, int n_in,
                              void* d_out, int out_size) {
    // Resolve inputs by size (element or byte counts); positional fallback.
    const float* A   = nullptr;
    const float* kg  = nullptr;
    const float* r   = nullptr;
    const float* cre = nullptr;
    const float* cim = nullptr;
    for (int i = 0; i < n_in; i++) {
        const float* p = (const float*)d_in[i];
        long long sz = in_sizes[i];
        if (sz == 9 || sz == 36)               A = p;
        else if (sz == 12 || sz == 48)         kg = p;
        else if (sz == 24000 || sz == 96000)   r = p;
        else if (sz == (long long)NB * NG || sz == (long long)NB * NG * 4) {
            if (!cre) cre = p; else cim = p;
        }
    }
    if (!A || !kg || !r || !cre || !cim) {
        if (n_in >= 5) {
            A   = (const float*)d_in[0];
            kg  = (const float*)d_in[1];
            cre = (const float*)d_in[2];
            cim = (const float*)d_in[3];
            r   = (const float*)d_in[4];
        } else {
            return;
        }
    }

    setup_kernel<<<1, 32>>>(A);
    bloch_kernel<<<NPTS / TP, NT>>>(cre, cim, r, kg, (float*)d_out, out_size);
}

// round 8
// speedup vs baseline: 3.7022x; 2.7768x over previous
#include <cuda_runtime.h>
#include <cuda_bf16.h>
#include <math.h>
#include <stdint.h>

#define NB     128     // batches
#define NG     8000    // plane waves (20^3)
#define NPTS   8000    // points
#define NGR    20      // grid per dim
#define KC     32      // K per stage
#define NSTAGE 250     // NG / KC
#define NTILE  64      // points per CTA
#define NCTA   125     // NPTS / NTILE
#define NT     256     // threads (8 warps, 4x2 warp grid)

// smem layout (bytes). Rows padded to 40 bf16 = 80B (conflict-free ldmatrix).
#define AS_BUF   61440                       // 6 variants x 128 rows x 80B
#define AS_VAR   10240
#define BS_BASE  122880                      // after 2 A buffers
#define BS_BUF   30720                       // 6 variants x 64 rows x 80B
#define BS_VAR   5120
#define SE_OFF   184320                      // 3 x 64 x 20 x float2 = 30720
#define SM_TOTAL 215040

__device__ float d_B[9];
__device__ float d_scale;
// variants: 0 crh 1 crl 2 cih 3 cil 4 csh 5 csl   (cs = cr + ci)
__device__ __align__(16) __nv_bfloat16 d_A[6][NB][NG];   // 12.3 MB

// ---------------- helpers ----------------
__device__ __forceinline__ uint32_t smem_u32(const void* p) {
    uint32_t a;
    asm("{ .reg .u64 t; cvta.to.shared.u64 t, %1; cvt.u32.u64 %0, t; }" : "=r"(a) : "l"(p));
    return a;
}
__device__ __forceinline__ float2 cmul(float2 a, float2 b) {
    return make_float2(a.x*b.x - a.y*b.y, a.x*b.y + a.y*b.x);
}

#define MMA16816(d, a, b0, b1) \
    asm volatile("mma.sync.aligned.m16n8k16.row.col.f32.bf16.bf16.f32 " \
        "{%0,%1,%2,%3}, {%4,%5,%6,%7}, {%8,%9}, {%0,%1,%2,%3};" \
        : "+f"((d)[0]), "+f"((d)[1]), "+f"((d)[2]), "+f"((d)[3]) \
        : "r"((a)[0]), "r"((a)[1]), "r"((a)[2]), "r"((a)[3]), "r"(b0), "r"(b1))

#define LDSM_X4(r, addr) \
    asm volatile("ldmatrix.sync.aligned.m8n8.x4.shared.b16 {%0,%1,%2,%3}, [%4];" \
        : "=r"((r)[0]), "=r"((r)[1]), "=r"((r)[2]), "=r"((r)[3]) : "r"(addr))

#define CPASYNC16(dst, src) \
    asm volatile("cp.async.cg.shared.global [%0], [%1], 16;" :: "r"(dst), "l"(src))

// ---------------- setup: reciprocal basis + scale ----------------
__global__ void setup_kernel(const float* __restrict__ A) {
    if (threadIdx.x == 0) {
        double a00=A[0],a01=A[1],a02=A[2];
        double a10=A[3],a11=A[4],a12=A[5];
        double a20=A[6],a21=A[7],a22=A[8];
        double c00 =  (a11*a22 - a12*a21);
        double c01 = -(a10*a22 - a12*a20);
        double c02 =  (a10*a21 - a11*a20);
        double c10 = -(a01*a22 - a02*a21);
        double c11 =  (a00*a22 - a02*a20);
        double c12 = -(a00*a21 - a01*a20);
        double c20 =  (a01*a12 - a02*a11);
        double c21 = -(a00*a12 - a02*a10);
        double c22 =  (a00*a11 - a01*a10);
        double det = a00*c00 + a01*c01 + a02*c02;
        double tp  = 6.283185307179586476925286766559;
        double s   = tp / det;
        d_B[0]=(float)(c00*s); d_B[1]=(float)(c01*s); d_B[2]=(float)(c02*s);
        d_B[3]=(float)(c10*s); d_B[4]=(float)(c11*s); d_B[5]=(float)(c12*s);
        d_B[6]=(float)(c20*s); d_B[7]=(float)(c21*s); d_B[8]=(float)(c22*s);
        d_scale = (float)(1.0 / sqrt(fabs(det)));
    }
}

// ---------------- prep: bf16 hi/lo splits of coefficients ----------------
__global__ void prep_kernel(const float* __restrict__ cre, const float* __restrict__ cim) {
    int b = blockIdx.x;
    for (int g = threadIdx.x; g < NG; g += 256) {
        float vr = cre[(size_t)b * NG + g];
        float vi = cim[(size_t)b * NG + g];
        float vs = vr + vi;
        __nv_bfloat16 rh = __float2bfloat16(vr);
        __nv_bfloat16 rl = __float2bfloat16(vr - __bfloat162float(rh));
        __nv_bfloat16 ih = __float2bfloat16(vi);
        __nv_bfloat16 il = __float2bfloat16(vi - __bfloat162float(ih));
        __nv_bfloat16 sh = __float2bfloat16(vs);
        __nv_bfloat16 sl = __float2bfloat16(vs - __bfloat162float(sh));
        d_A[0][b][g] = rh;  d_A[1][b][g] = rl;
        d_A[2][b][g] = ih;  d_A[3][b][g] = il;
        d_A[4][b][g] = sh;  d_A[5][b][g] = sl;
    }
}

// ---------------- mma building blocks ----------------
__device__ __forceinline__ void mma_set(
    float S[2][4][4], uint32_t aH, uint32_t aL, uint32_t bH, uint32_t bL)
{
    uint32_t ah[2][4], al[2][4], bh[2][4], bl[2][4];
    #pragma unroll
    for (int mt = 0; mt < 2; mt++) {
        LDSM_X4(ah[mt], aH + mt * 16 * 80);
        LDSM_X4(al[mt], aL + mt * 16 * 80);
    }
    #pragma unroll
    for (int np = 0; np < 2; np++) {
        LDSM_X4(bh[np], bH + np * 16 * 80);
        LDSM_X4(bl[np], bL + np * 16 * 80);
    }
    #pragma unroll
    for (int mt = 0; mt < 2; mt++) {
        #pragma unroll
        for (int nt = 0; nt < 4; nt++) {
            int np = nt >> 1, q = (nt & 1) * 2;
            MMA16816(S[mt][nt], ah[mt], bh[np][q], bh[np][q+1]);   // hi*hi
            MMA16816(S[mt][nt], al[mt], bh[np][q], bh[np][q+1]);   // lo*hi
            MMA16816(S[mt][nt], ah[mt], bl[np][q], bl[np][q+1]);   // hi*lo
        }
    }
}

// ---------------- main kernel ----------------
__global__ void __launch_bounds__(NT, 1)
mma_kernel(const float* __restrict__ r, const float* __restrict__ kg,
           float* __restrict__ out, int out_elems)
{
    extern __shared__ char smem[];
    uint32_t sb = smem_u32(smem);
    const int tid  = threadIdx.x;
    const int wid  = tid >> 5;
    const int lane = tid & 31;
    const int p0   = blockIdx.x * NTILE;

    // e tables: se[(d*64+p)*20+i] = exp(i * m(i) * (B_d . r_p))
    float2* se = (float2*)(smem + SE_OFF);
    for (int t = tid; t < 3 * NTILE * NGR; t += NT) {
        int d   = t / (NTILE * NGR);
        int rem = t - d * NTILE * NGR;
        int p   = rem / NGR;
        int i   = rem - p * NGR;
        int m   = (i < NGR/2) ? i : i - NGR;
        const float* rp = r + (p0 + p) * 3;
        float u = d_B[3*d]*rp[0] + d_B[3*d+1]*rp[1] + d_B[3*d+2]*rp[2];
        float sv, cv;
        sincosf((float)m * u, &sv, &cv);
        se[(d * NTILE + p) * NGR + i] = make_float2(cv, sv);
    }

    // accumulators (Karatsuba): S1=cr*pr, S2=ci*pi, S3=cs*ps
    float S1[2][4][4], S2[2][4][4], S3[2][4][4];
    #pragma unroll
    for (int mt = 0; mt < 2; mt++)
        #pragma unroll
        for (int nt = 0; nt < 4; nt++)
            #pragma unroll
            for (int q = 0; q < 4; q++) { S1[mt][nt][q]=0.f; S2[mt][nt][q]=0.f; S3[mt][nt][q]=0.f; }

    // per-thread ldmatrix row offsets
    const uint32_t aRowOff = (lane & 15) * 80 + (lane >> 4) * 16;
    const uint32_t bRowOff = (((lane >> 4) & 1) * 8 + (lane & 7)) * 80 + ((lane >> 3) & 1) * 16;
    const int m0 = (wid & 3) * 32;
    const int n0 = (wid >> 2) * 32;
    const uint32_t amBase = (uint32_t)m0 * 80 + aRowOff;
    const uint32_t bnBase = (uint32_t)n0 * 80 + bRowOff;

    // ---- prologue: cp.async stage 0 into A buffer 0 ----
    {
        #pragma unroll
        for (int j = 0; j < 12; j++) {
            int c = tid + NT * j;
            int v = c >> 9;
            int rem = c & 511;
            int row = rem >> 2;
            int q = rem & 3;
            const char* src = (const char*)d_A
                + (((size_t)v * NB + row) * NG) * 2 + q * 16;
            uint32_t dst = sb + v * AS_VAR + row * 80 + q * 16;
            CPASYNC16(dst, src);
        }
        asm volatile("cp.async.commit_group;" ::: "memory");
    }
    __syncthreads();   // e tables ready

    for (int s = 0; s < NSTAGE; s++) {
        const int cur = s & 1;
        const uint32_t aBuf = sb + cur * AS_BUF;
        const uint32_t bBuf = sb + BS_BASE + cur * BS_BUF;

        // ---- generate phase B tiles for stage s into Bs[cur] ----
        {
            int gl = lane;                 // g within chunk = lane
            int pq = wid;                  // warp -> 8 points
            int g  = s * KC + gl;
            int i1 = g / 400;
            int i2 = (g / 20) % 20;
            int i3 = g % 20;
            #pragma unroll
            for (int pi = 0; pi < 8; pi++) {
                int p = pq * 8 + pi;
                float2 e1 = se[(0 * NTILE + p) * NGR + i1];
                float2 e2 = se[(1 * NTILE + p) * NGR + i2];
                float2 e3 = se[(2 * NTILE + p) * NGR + i3];
                float2 ph = cmul(cmul(e1, e2), e3);
                float pr = ph.x, pim = ph.y, ps = pr + pim;
                __nv_bfloat16 prh = __float2bfloat16(pr);
                __nv_bfloat16 prl = __float2bfloat16(pr - __bfloat162float(prh));
                __nv_bfloat16 pih = __float2bfloat16(pim);
                __nv_bfloat16 pil = __float2bfloat16(pim - __bfloat162float(pih));
                __nv_bfloat16 psh = __float2bfloat16(ps);
                __nv_bfloat16 psl = __float2bfloat16(ps - __bfloat162float(psh));
                uint32_t off = (uint32_t)p * 80 + gl * 2;
                char* bptr = smem + BS_BASE + cur * BS_BUF;
                *(__nv_bfloat16*)(bptr + 0 * BS_VAR + off) = prh;
                *(__nv_bfloat16*)(bptr + 1 * BS_VAR + off) = prl;
                *(__nv_bfloat16*)(bptr + 2 * BS_VAR + off) = pih;
                *(__nv_bfloat16*)(bptr + 3 * BS_VAR + off) = pil;
                *(__nv_bfloat16*)(bptr + 4 * BS_VAR + off) = psh;
                *(__nv_bfloat16*)(bptr + 5 * BS_VAR + off) = psl;
            }
        }
        __syncthreads();   // (a) all mma(s-1) done + phases(s) written

        // ---- issue cp.async for stage s+1 into the other A buffer ----
        if (s + 1 < NSTAGE) {
            uint32_t dbase = sb + (cur ^ 1) * AS_BUF;
            #pragma unroll
            for (int j = 0; j < 12; j++) {
                int c = tid + NT * j;
                int v = c >> 9;
                int rem = c & 511;
                int row = rem >> 2;
                int q = rem & 3;
                const char* src = (const char*)d_A
                    + (((size_t)v * NB + row) * NG + (size_t)(s + 1) * KC) * 2 + q * 16;
                uint32_t dst = dbase + v * AS_VAR + row * 80 + q * 16;
                CPASYNC16(dst, src);
            }
            asm volatile("cp.async.commit_group;" ::: "memory");
            asm volatile("cp.async.wait_group 1;" ::: "memory");
        } else {
            asm volatile("cp.async.wait_group 0;" ::: "memory");
        }
        __syncthreads();   // (b) A(s) visible to all threads

        // ---- mma: 2 k16-steps x 3 sets x 3 split-products ----
        #pragma unroll
        for (int k16 = 0; k16 < 2; k16++) {
            uint32_t kb = k16 * 32;   // 16 elems * 2B
            mma_set(S1, aBuf + 0*AS_VAR + amBase + kb, aBuf + 1*AS_VAR + amBase + kb,
                        bBuf + 0*BS_VAR + bnBase + kb, bBuf + 1*BS_VAR + bnBase + kb);
            mma_set(S2, aBuf + 2*AS_VAR + amBase + kb, aBuf + 3*AS_VAR + amBase + kb,
                        bBuf + 2*BS_VAR + bnBase + kb, bBuf + 3*BS_VAR + bnBase + kb);
            mma_set(S3, aBuf + 4*AS_VAR + amBase + kb, aBuf + 5*AS_VAR + amBase + kb,
                        bBuf + 4*BS_VAR + bnBase + kb, bBuf + 5*BS_VAR + bnBase + kb);
        }
    }

    // ---- epilogue: Re = S1-S2, Im = S3-S1-S2; rotate by k, scale, store ----
    const bool cplx = (out_elems >= 2 * NB * NPTS);
    const float scale = d_scale;
    #pragma unroll
    for (int mt = 0; mt < 2; mt++) {
        #pragma unroll
        for (int nt = 0; nt < 4; nt++) {
            #pragma unroll
            for (int q = 0; q < 4; q++) {
                float v1 = S1[mt][nt][q], v2 = S2[mt][nt][q], v3 = S3[mt][nt][q];
                float Re = v1 - v2;
                float Im = v3 - v1 - v2;
                int b = m0 + mt * 16 + (lane >> 2) + (q >> 1) * 8;
                int p = p0 + n0 + nt * 8 + (lane & 3) * 2 + (q & 1);
                int kq = (b >> 4) & 3;
                const float* rp = r + p * 3;
                float ang = kg[3*kq]*rp[0] + kg[3*kq+1]*rp[1] + kg[3*kq+2]*rp[2];
                float sv, cv;
                sincosf(ang, &sv, &cv);
                float ore = (Re * cv - Im * sv) * scale;
                float oim = (Re * sv + Im * cv) * scale;
                size_t idx = (size_t)b * NPTS + p;
                if (cplx) ((float2*)out)[idx] = make_float2(ore, oim);
                else      out[idx] = ore;
            }
        }
    }
}

extern "C" void kernel_launch(void* const* d_in, const int* in_sizes, int n_in,
                              void* d_out, int out_size) {
    const float* A   = nullptr;
    const float* kg  = nullptr;
    const float* r   = nullptr;
    const float* cre = nullptr;
    const float* cim = nullptr;
    for (int i = 0; i < n_in; i++) {
        const float* p = (const float*)d_in[i];
        long long sz = in_sizes[i];
        if (sz == 9 || sz == 36)               A = p;
        else if (sz == 12 || sz == 48)         kg = p;
        else if (sz == 24000 || sz == 96000)   r = p;
        else if (sz == (long long)NB * NG || sz == (long long)NB * NG * 4) {
            if (!cre) cre = p; else cim = p;
        }
    }
    if (!A || !kg || !r || !cre || !cim) {
        if (n_in >= 5) {
            A   = (const float*)d_in[0];
            kg  = (const float*)d_in[1];
            cre = (const float*)d_in[2];
            cim = (const float*)d_in[3];
            r   = (const float*)d_in[4];
        } else {
            return;
        }
    }

    static bool attr_set = false;
    if (!attr_set) {
        cudaFuncSetAttribute(mma_kernel, cudaFuncAttributeMaxDynamicSharedMemorySize, SM_TOTAL);
        attr_set = true;
    }

    setup_kernel<<<1, 32>>>(A);
    prep_kernel<<<NB, 256>>>(cre, cim);
    mma_kernel<<<NCTA, NT, SM_TOTAL>>>(r, kg, (float*)d_out, out_size);
}

// round 9
// speedup vs baseline: 3.7555x; 1.0144x over previous
#include <cuda_runtime.h>
#include <cuda_bf16.h>
#include <math.h>
#include <stdint.h>

#define NB     128     // batches
#define NG     8000    // plane waves (20^3)
#define NPTS   8000    // points
#define NGR    20      // grid per dim
#define KC     32      // K per stage
#define NSTAGE 250     // NG / KC
#define NTILE  64      // points per CTA
#define NCTA   125     // NPTS / NTILE
#define NT     512     // threads (16 warps, 4x4 warp grid: m32 x n16 per warp)

// smem layout (bytes). Rows padded to 40 bf16 = 80B (conflict-free ldmatrix).
#define AS_BUF   61440                       // 6 variants x 128 rows x 80B
#define AS_VAR   10240
#define BS_BASE  122880                      // after 2 A buffers
#define BS_BUF   30720                       // 6 variants x 64 rows x 80B
#define BS_VAR   5120
#define SE_OFF   184320                      // 3 x 64 x 20 x float2 = 30720
#define SM_TOTAL 215040

__device__ float d_B[9];
__device__ float d_scale;
// variants: 0 crh 1 crl 2 cih 3 cil 4 csh 5 csl   (cs = cr + ci)
__device__ __align__(16) __nv_bfloat16 d_A[6][NB][NG];   // 12.3 MB

// ---------------- helpers ----------------
__device__ __forceinline__ uint32_t smem_u32(const void* p) {
    uint32_t a;
    asm("{ .reg .u64 t; cvta.to.shared.u64 t, %1; cvt.u32.u64 %0, t; }" : "=r"(a) : "l"(p));
    return a;
}
__device__ __forceinline__ float2 cmul(float2 a, float2 b) {
    return make_float2(a.x*b.x - a.y*b.y, a.x*b.y + a.y*b.x);
}

#define MMA16816(d, a, b0, b1) \
    asm volatile("mma.sync.aligned.m16n8k16.row.col.f32.bf16.bf16.f32 " \
        "{%0,%1,%2,%3}, {%4,%5,%6,%7}, {%8,%9}, {%0,%1,%2,%3};" \
        : "+f"((d)[0]), "+f"((d)[1]), "+f"((d)[2]), "+f"((d)[3]) \
        : "r"((a)[0]), "r"((a)[1]), "r"((a)[2]), "r"((a)[3]), "r"(b0), "r"(b1))

#define LDSM_X4(r, addr) \
    asm volatile("ldmatrix.sync.aligned.m8n8.x4.shared.b16 {%0,%1,%2,%3}, [%4];" \
        : "=r"((r)[0]), "=r"((r)[1]), "=r"((r)[2]), "=r"((r)[3]) : "r"(addr))

#define CPASYNC16(dst, src) \
    asm volatile("cp.async.cg.shared.global [%0], [%1], 16;" :: "r"(dst), "l"(src))

// ---------------- prep: setup (block 0) + bf16 hi/lo splits ----------------
__global__ void prep_kernel(const float* __restrict__ cre, const float* __restrict__ cim,
                            const float* __restrict__ A) {
    if (blockIdx.x == 0 && threadIdx.x == 0) {
        double a00=A[0],a01=A[1],a02=A[2];
        double a10=A[3],a11=A[4],a12=A[5];
        double a20=A[6],a21=A[7],a22=A[8];
        double c00 =  (a11*a22 - a12*a21);
        double c01 = -(a10*a22 - a12*a20);
        double c02 =  (a10*a21 - a11*a20);
        double c10 = -(a01*a22 - a02*a21);
        double c11 =  (a00*a22 - a02*a20);
        double c12 = -(a00*a21 - a01*a20);
        double c20 =  (a01*a12 - a02*a11);
        double c21 = -(a00*a12 - a02*a10);
        double c22 =  (a00*a11 - a01*a10);
        double det = a00*c00 + a01*c01 + a02*c02;
        double tp  = 6.283185307179586476925286766559;
        double s   = tp / det;
        d_B[0]=(float)(c00*s); d_B[1]=(float)(c01*s); d_B[2]=(float)(c02*s);
        d_B[3]=(float)(c10*s); d_B[4]=(float)(c11*s); d_B[5]=(float)(c12*s);
        d_B[6]=(float)(c20*s); d_B[7]=(float)(c21*s); d_B[8]=(float)(c22*s);
        d_scale = (float)(1.0 / sqrt(fabs(det)));
    }
    int b = blockIdx.x;
    for (int g = threadIdx.x; g < NG; g += 256) {
        float vr = cre[(size_t)b * NG + g];
        float vi = cim[(size_t)b * NG + g];
        float vs = vr + vi;
        __nv_bfloat16 rh = __float2bfloat16(vr);
        __nv_bfloat16 rl = __float2bfloat16(vr - __bfloat162float(rh));
        __nv_bfloat16 ih = __float2bfloat16(vi);
        __nv_bfloat16 il = __float2bfloat16(vi - __bfloat162float(ih));
        __nv_bfloat16 sh = __float2bfloat16(vs);
        __nv_bfloat16 sl = __float2bfloat16(vs - __bfloat162float(sh));
        d_A[0][b][g] = rh;  d_A[1][b][g] = rl;
        d_A[2][b][g] = ih;  d_A[3][b][g] = il;
        d_A[4][b][g] = sh;  d_A[5][b][g] = sl;
    }
}

// ---------------- mma building block: m32 x n16 x k16 with hi/lo split ----------------
__device__ __forceinline__ void mma_set(
    float S[2][2][4], uint32_t aH, uint32_t aL, uint32_t bH, uint32_t bL)
{
    uint32_t ah[2][4], al[2][4], bh[4], bl[4];
    #pragma unroll
    for (int mt = 0; mt < 2; mt++) {
        LDSM_X4(ah[mt], aH + mt * 16 * 80);
        LDSM_X4(al[mt], aL + mt * 16 * 80);
    }
    LDSM_X4(bh, bH);
    LDSM_X4(bl, bL);
    #pragma unroll
    for (int mt = 0; mt < 2; mt++) {
        #pragma unroll
        for (int nt = 0; nt < 2; nt++) {
            int q = nt * 2;
            MMA16816(S[mt][nt], ah[mt], bh[q], bh[q+1]);   // hi*hi
            MMA16816(S[mt][nt], al[mt], bh[q], bh[q+1]);   // lo*hi
            MMA16816(S[mt][nt], ah[mt], bl[q], bl[q+1]);   // hi*lo
        }
    }
}

// ---------------- main kernel ----------------
__global__ void __launch_bounds__(NT, 1)
mma_kernel(const float* __restrict__ r, const float* __restrict__ kg,
           float* __restrict__ out, int out_elems)
{
    extern __shared__ char smem[];
    uint32_t sb = smem_u32(smem);
    const int tid  = threadIdx.x;
    const int wid  = tid >> 5;
    const int lane = tid & 31;
    const int p0   = blockIdx.x * NTILE;

    // e tables: se[(d*64+p)*20+i] = exp(i * m(i) * (B_d . r_p))
    float2* se = (float2*)(smem + SE_OFF);
    for (int t = tid; t < 3 * NTILE * NGR; t += NT) {
        int d   = t / (NTILE * NGR);
        int rem = t - d * NTILE * NGR;
        int p   = rem / NGR;
        int i   = rem - p * NGR;
        int m   = (i < NGR/2) ? i : i - NGR;
        const float* rp = r + (p0 + p) * 3;
        float u = d_B[3*d]*rp[0] + d_B[3*d+1]*rp[1] + d_B[3*d+2]*rp[2];
        float sv, cv;
        sincosf((float)m * u, &sv, &cv);
        se[(d * NTILE + p) * NGR + i] = make_float2(cv, sv);
    }

    // accumulators (Karatsuba): S1=cr*pr, S2=ci*pi, S3=cs*ps
    float S1[2][2][4], S2[2][2][4], S3[2][2][4];
    #pragma unroll
    for (int mt = 0; mt < 2; mt++)
        #pragma unroll
        for (int nt = 0; nt < 2; nt++)
            #pragma unroll
            for (int q = 0; q < 4; q++) { S1[mt][nt][q]=0.f; S2[mt][nt][q]=0.f; S3[mt][nt][q]=0.f; }

    // per-thread ldmatrix row offsets
    const uint32_t aRowOff = (lane & 15) * 80 + (lane >> 4) * 16;
    const uint32_t bRowOff = (((lane >> 4) & 1) * 8 + (lane & 7)) * 80 + ((lane >> 3) & 1) * 16;
    const int m0 = (wid & 3) * 32;     // batch block (4 m-warps)
    const int n0 = (wid >> 2) * 16;    // point block (4 n-warps)
    const uint32_t amBase = (uint32_t)m0 * 80 + aRowOff;
    const uint32_t bnBase = (uint32_t)n0 * 80 + bRowOff;

    // ---- prologue: cp.async stage 0 into A buffer 0 (3072 chunks, 6/thread) ----
    {
        #pragma unroll
        for (int j = 0; j < 6; j++) {
            int c = tid + NT * j;
            int v = c >> 9;
            int rem = c & 511;
            int row = rem >> 2;
            int q = rem & 3;
            const char* src = (const char*)d_A + (((size_t)v * NB + row) * NG) * 2 + q * 16;
            uint32_t dst = sb + v * AS_VAR + row * 80 + q * 16;
            CPASYNC16(dst, src);
        }
        asm volatile("cp.async.commit_group;" ::: "memory");
    }
    __syncthreads();   // e tables ready

    for (int s = 0; s < NSTAGE; s++) {
        const int cur = s & 1;
        const uint32_t aBuf = sb + cur * AS_BUF;
        const uint32_t bBuf = sb + BS_BASE + cur * BS_BUF;

        // ---- generate phase B tiles for stage s (each warp: 4 points) ----
        {
            int gl = lane;
            int g  = s * KC + gl;
            int i1 = g / 400;
            int i2 = (g / 20) % 20;
            int i3 = g % 20;
            #pragma unroll
            for (int pi = 0; pi < 4; pi++) {
                int p = wid * 4 + pi;
                float2 e1 = se[(0 * NTILE + p) * NGR + i1];
                float2 e2 = se[(1 * NTILE + p) * NGR + i2];
                float2 e3 = se[(2 * NTILE + p) * NGR + i3];
                float2 ph = cmul(cmul(e1, e2), e3);
                float pr = ph.x, pim = ph.y, ps = pr + pim;
                __nv_bfloat16 prh = __float2bfloat16(pr);
                __nv_bfloat16 prl = __float2bfloat16(pr - __bfloat162float(prh));
                __nv_bfloat16 pih = __float2bfloat16(pim);
                __nv_bfloat16 pil = __float2bfloat16(pim - __bfloat162float(pih));
                __nv_bfloat16 psh = __float2bfloat16(ps);
                __nv_bfloat16 psl = __float2bfloat16(ps - __bfloat162float(psh));
                uint32_t off = (uint32_t)p * 80 + gl * 2;
                char* bptr = smem + BS_BASE + cur * BS_BUF;
                *(__nv_bfloat16*)(bptr + 0 * BS_VAR + off) = prh;
                *(__nv_bfloat16*)(bptr + 1 * BS_VAR + off) = prl;
                *(__nv_bfloat16*)(bptr + 2 * BS_VAR + off) = pih;
                *(__nv_bfloat16*)(bptr + 3 * BS_VAR + off) = pil;
                *(__nv_bfloat16*)(bptr + 4 * BS_VAR + off) = psh;
                *(__nv_bfloat16*)(bptr + 5 * BS_VAR + off) = psl;
            }
        }
        __syncthreads();   // (a) mma(s-1) done everywhere + phases(s) visible

        // ---- issue cp.async for stage s+1 into the other A buffer ----
        if (s + 1 < NSTAGE) {
            uint32_t dbase = sb + (cur ^ 1) * AS_BUF;
            #pragma unroll
            for (int j = 0; j < 6; j++) {
                int c = tid + NT * j;
                int v = c >> 9;
                int rem = c & 511;
                int row = rem >> 2;
                int q = rem & 3;
                const char* src = (const char*)d_A
                    + (((size_t)v * NB + row) * NG + (size_t)(s + 1) * KC) * 2 + q * 16;
                uint32_t dst = dbase + v * AS_VAR + row * 80 + q * 16;
                CPASYNC16(dst, src);
            }
            asm volatile("cp.async.commit_group;" ::: "memory");
            asm volatile("cp.async.wait_group 1;" ::: "memory");
        } else {
            asm volatile("cp.async.wait_group 0;" ::: "memory");
        }
        __syncthreads();   // (b) A(s) visible

        // ---- mma: 2 k16-steps x 3 sets x (4 tiles x 3 split-products) ----
        #pragma unroll
        for (int k16 = 0; k16 < 2; k16++) {
            uint32_t kb = k16 * 32;
            mma_set(S1, aBuf + 0*AS_VAR + amBase + kb, aBuf + 1*AS_VAR + amBase + kb,
                        bBuf + 0*BS_VAR + bnBase + kb, bBuf + 1*BS_VAR + bnBase + kb);
            mma_set(S2, aBuf + 2*AS_VAR + amBase + kb, aBuf + 3*AS_VAR + amBase + kb,
                        bBuf + 2*BS_VAR + bnBase + kb, bBuf + 3*BS_VAR + bnBase + kb);
            mma_set(S3, aBuf + 4*AS_VAR + amBase + kb, aBuf + 5*AS_VAR + amBase + kb,
                        bBuf + 4*BS_VAR + bnBase + kb, bBuf + 5*BS_VAR + bnBase + kb);
        }
    }

    // ---- epilogue: Re = S1-S2, Im = S3-S1-S2; rotate by k, scale, store ----
    const bool cplx = (out_elems >= 2 * NB * NPTS);
    const float scale = d_scale;
    #pragma unroll
    for (int mt = 0; mt < 2; mt++) {
        #pragma unroll
        for (int nt = 0; nt < 2; nt++) {
            #pragma unroll
            for (int q = 0; q < 4; q++) {
                float v1 = S1[mt][nt][q], v2 = S2[mt][nt][q], v3 = S3[mt][nt][q];
                float Re = v1 - v2;
                float Im = v3 - v1 - v2;
                int b = m0 + mt * 16 + (lane >> 2) + (q >> 1) * 8;
                int p = p0 + n0 + nt * 8 + (lane & 3) * 2 + (q & 1);
                int kq = (b >> 4) & 3;
                const float* rp = r + p * 3;
                float ang = kg[3*kq]*rp[0] + kg[3*kq+1]*rp[1] + kg[3*kq+2]*rp[2];
                float sv, cv;
                sincosf(ang, &sv, &cv);
                float ore = (Re * cv - Im * sv) * scale;
                float oim = (Re * sv + Im * cv) * scale;
                size_t idx = (size_t)b * NPTS + p;
                if (cplx) ((float2*)out)[idx] = make_float2(ore, oim);
                else      out[idx] = ore;
            }
        }
    }
}

extern "C" void kernel_launch(void* const* d_in, const int* in_sizes, int n_in,
                              void* d_out, int out_size) {
    const float* A   = nullptr;
    const float* kg  = nullptr;
    const float* r   = nullptr;
    const float* cre = nullptr;
    const float* cim = nullptr;
    for (int i = 0; i < n_in; i++) {
        const float* p = (const float*)d_in[i];
        long long sz = in_sizes[i];
        if (sz == 9 || sz == 36)               A = p;
        else if (sz == 12 || sz == 48)         kg = p;
        else if (sz == 24000 || sz == 96000)   r = p;
        else if (sz == (long long)NB * NG || sz == (long long)NB * NG * 4) {
            if (!cre) cre = p; else cim = p;
        }
    }
    if (!A || !kg || !r || !cre || !cim) {
        if (n_in >= 5) {
            A   = (const float*)d_in[0];
            kg  = (const float*)d_in[1];
            cre = (const float*)d_in[2];
            cim = (const float*)d_in[3];
            r   = (const float*)d_in[4];
        } else {
            return;
        }
    }

    static bool attr_set = false;
    if (!attr_set) {
        cudaFuncSetAttribute(mma_kernel, cudaFuncAttributeMaxDynamicSharedMemorySize, SM_TOTAL);
        attr_set = true;
    }

    prep_kernel<<<NB, 256>>>(cre, cim, A);
    mma_kernel<<<NCTA, NT, SM_TOTAL>>>(r, kg, (float*)d_out, out_size);
}

// round 10
// speedup vs baseline: 4.9080x; 1.3069x over previous
#include <cuda_runtime.h>
#include <cuda_bf16.h>
#include <math.h>
#include <stdint.h>

#define NB     128     // batches
#define NG     8000    // plane waves (20^3)
#define NPTS   8000    // points
#define NGR    20      // grid per dim
#define KC     32      // K per stage
#define NSTAGE 250     // NG / KC
#define NTILE  64      // points per CTA
#define NCTA   125     // NPTS / NTILE
#define NT     256     // threads (8 warps, 4m x 2n grid: m32 x n32 per warp)

// A stage chunk: 6 variants x 128 rows x 80B (64B data + 16B pad) = 61440 B
#define STG_BYTES 61440
#define AS_VAR    10240
#define B_OFF     122880                     // after 2 A buffers
#define BS_BUF    30720                      // 6 variants x 64 rows x 80B
#define BS_VAR    5120
#define SE_OFF    184320                     // 3 x 64 x 20 x float2 = 30720
#define MB_OFF    215040                     // 2 mbarriers
#define SM_TOTAL  215072

__device__ float d_B[9];
__device__ float d_scale;
// stage-major, ldmatrix-ready (80B rows, pad zeroed):
// d_A2[((s*6 + v)*128 + row)*40 + g]   v: 0 crh 1 crl 2 cih 3 cil 4 csh 5 csl
__device__ __align__(128) __nv_bfloat16 d_A2[(size_t)NSTAGE * 6 * NB * 40];  // 15.36 MB

// ---------------- helpers ----------------
__device__ __forceinline__ uint32_t smem_u32(const void* p) {
    uint32_t a;
    asm("{ .reg .u64 t; cvta.to.shared.u64 t, %1; cvt.u32.u64 %0, t; }" : "=r"(a) : "l"(p));
    return a;
}
__device__ __forceinline__ float2 cmul(float2 a, float2 b) {
    return make_float2(a.x*b.x - a.y*b.y, a.x*b.y + a.y*b.x);
}

#define MMA16816(d, a, b0, b1) \
    asm volatile("mma.sync.aligned.m16n8k16.row.col.f32.bf16.bf16.f32 " \
        "{%0,%1,%2,%3}, {%4,%5,%6,%7}, {%8,%9}, {%0,%1,%2,%3};" \
        : "+f"((d)[0]), "+f"((d)[1]), "+f"((d)[2]), "+f"((d)[3]) \
        : "r"((a)[0]), "r"((a)[1]), "r"((a)[2]), "r"((a)[3]), "r"(b0), "r"(b1))

#define LDSM_X4(r, addr) \
    asm volatile("ldmatrix.sync.aligned.m8n8.x4.shared.b16 {%0,%1,%2,%3}, [%4];" \
        : "=r"((r)[0]), "=r"((r)[1]), "=r"((r)[2]), "=r"((r)[3]) : "r"(addr))

#define MBAR_WAIT(mbar, parity) do { \
    uint32_t _m = (mbar); uint32_t _p = (parity); uint32_t _d; \
    asm volatile("{ .reg .pred p; mbarrier.try_wait.parity.acquire.cta.shared::cta.b64 p, [%1], %2; selp.b32 %0, 1, 0, p; }" \
        : "=r"(_d) : "r"(_m), "r"(_p) : "memory"); \
    if (!_d) { \
        asm volatile("{ .reg .pred P1; WL_%=: mbarrier.try_wait.parity.acquire.cta.shared::cta.b64 P1, [%0], %1, 0x989680; @P1 bra.uni WD_%=; bra.uni WL_%=; WD_%=: }" \
            :: "r"(_m), "r"(_p) : "memory"); \
    } \
} while (0)

// ---------------- prep: setup (block 0) + stage-major bf16 splits ----------------
__global__ void prep_kernel(const float* __restrict__ cre, const float* __restrict__ cim,
                            const float* __restrict__ A) {
    if (blockIdx.x == 0 && threadIdx.x == 0) {
        double a00=A[0],a01=A[1],a02=A[2];
        double a10=A[3],a11=A[4],a12=A[5];
        double a20=A[6],a21=A[7],a22=A[8];
        double c00 =  (a11*a22 - a12*a21);
        double c01 = -(a10*a22 - a12*a20);
        double c02 =  (a10*a21 - a11*a20);
        double c10 = -(a01*a22 - a02*a21);
        double c11 =  (a00*a22 - a02*a20);
        double c12 = -(a00*a21 - a01*a20);
        double c20 =  (a01*a12 - a02*a11);
        double c21 = -(a00*a12 - a02*a10);
        double c22 =  (a00*a11 - a01*a10);
        double det = a00*c00 + a01*c01 + a02*c02;
        double tp  = 6.283185307179586476925286766559;
        double s   = tp / det;
        d_B[0]=(float)(c00*s); d_B[1]=(float)(c01*s); d_B[2]=(float)(c02*s);
        d_B[3]=(float)(c10*s); d_B[4]=(float)(c11*s); d_B[5]=(float)(c12*s);
        d_B[6]=(float)(c20*s); d_B[7]=(float)(c21*s); d_B[8]=(float)(c22*s);
        d_scale = (float)(1.0 / sqrt(fabs(det)));
    }
    int b = blockIdx.x;
    for (int g = threadIdx.x; g < NG; g += 256) {
        int s  = g >> 5;
        int gl = g & 31;
        float vr = cre[(size_t)b * NG + g];
        float vi = cim[(size_t)b * NG + g];
        float vs = vr + vi;
        __nv_bfloat16 rh = __float2bfloat16(vr);
        __nv_bfloat16 rl = __float2bfloat16(vr - __bfloat162float(rh));
        __nv_bfloat16 ih = __float2bfloat16(vi);
        __nv_bfloat16 il = __float2bfloat16(vi - __bfloat162float(ih));
        __nv_bfloat16 sh = __float2bfloat16(vs);
        __nv_bfloat16 sl = __float2bfloat16(vs - __bfloat162float(sh));
        size_t base = ((size_t)s * 6 * NB + b) * 40 + gl;
        d_A2[base + (size_t)0 * NB * 40] = rh;
        d_A2[base + (size_t)1 * NB * 40] = rl;
        d_A2[base + (size_t)2 * NB * 40] = ih;
        d_A2[base + (size_t)3 * NB * 40] = il;
        d_A2[base + (size_t)4 * NB * 40] = sh;
        d_A2[base + (size_t)5 * NB * 40] = sl;
    }
    // zero the 16B row padding (deterministic every call)
    __nv_bfloat16 z = __float2bfloat16(0.0f);
    for (int t = threadIdx.x; t < NSTAGE * 6 * 8; t += 256) {
        int s = t / 48;
        int rem = t - s * 48;
        int v = rem >> 3;
        int q = rem & 7;
        d_A2[(((size_t)s * 6 + v) * NB + b) * 40 + 32 + q] = z;
    }
}

// ---------------- mma building block: m32 x n32 x k16 with hi/lo split ----------------
__device__ __forceinline__ void mma_set(
    float S[2][4][4], uint32_t aH, uint32_t aL, uint32_t bH, uint32_t bL)
{
    uint32_t ah[2][4], al[2][4], bh[2][4], bl[2][4];
    #pragma unroll
    for (int mt = 0; mt < 2; mt++) {
        LDSM_X4(ah[mt], aH + mt * 16 * 80);
        LDSM_X4(al[mt], aL + mt * 16 * 80);
    }
    #pragma unroll
    for (int np = 0; np < 2; np++) {
        LDSM_X4(bh[np], bH + np * 16 * 80);
        LDSM_X4(bl[np], bL + np * 16 * 80);
    }
    #pragma unroll
    for (int mt = 0; mt < 2; mt++) {
        #pragma unroll
        for (int nt = 0; nt < 4; nt++) {
            int np = nt >> 1, q = (nt & 1) * 2;
            MMA16816(S[mt][nt], ah[mt], bh[np][q], bh[np][q+1]);   // hi*hi
            MMA16816(S[mt][nt], al[mt], bh[np][q], bh[np][q+1]);   // lo*hi
            MMA16816(S[mt][nt], ah[mt], bl[np][q], bl[np][q+1]);   // hi*lo
        }
    }
}

// ---------------- main kernel ----------------
__global__ void __launch_bounds__(NT, 1)
mma_kernel(const float* __restrict__ r, const float* __restrict__ kg,
           float* __restrict__ out, int out_elems)
{
    extern __shared__ char smem[];
    uint32_t sb = smem_u32(smem);
    const int tid  = threadIdx.x;
    const int wid  = tid >> 5;
    const int lane = tid & 31;
    const int p0   = blockIdx.x * NTILE;
    const uint32_t mbar0 = sb + MB_OFF;
    const uint32_t mbar1 = sb + MB_OFF + 8;

    // e tables: se[(d*64+p)*20+i] = exp(i * m(i) * (B_d . r_p))
    float2* se = (float2*)(smem + SE_OFF);
    for (int t = tid; t < 3 * NTILE * NGR; t += NT) {
        int d   = t / (NTILE * NGR);
        int rem = t - d * NTILE * NGR;
        int p   = rem / NGR;
        int i   = rem - p * NGR;
        int m   = (i < NGR/2) ? i : i - NGR;
        const float* rp = r + (p0 + p) * 3;
        float u = d_B[3*d]*rp[0] + d_B[3*d+1]*rp[1] + d_B[3*d+2]*rp[2];
        float sv, cv;
        sincosf((float)m * u, &sv, &cv);
        se[(d * NTILE + p) * NGR + i] = make_float2(cv, sv);
    }
    if (tid == 0) {
        asm volatile("mbarrier.init.shared.b64 [%0], %1;" :: "r"(mbar0), "r"(1u) : "memory");
        asm volatile("mbarrier.init.shared.b64 [%0], %1;" :: "r"(mbar1), "r"(1u) : "memory");
    }
    __syncthreads();

    // prologue: bulk-copy stage 0 into A buffer 0
    if (tid == 0) {
        asm volatile("mbarrier.arrive.expect_tx.shared.b64 _, [%0], %1;"
                     :: "r"(mbar0), "r"((uint32_t)STG_BYTES) : "memory");
        const char* src = (const char*)d_A2;
        asm volatile("cp.async.bulk.shared::cluster.global.mbarrier::complete_tx::bytes [%0], [%1], %2, [%3];"
                     :: "r"(sb), "l"(src), "r"((uint32_t)STG_BYTES), "r"(mbar0) : "memory");
    }

    // accumulators (Karatsuba): S1=cr*pr, S2=ci*pi, S3=cs*ps
    float S1[2][4][4], S2[2][4][4], S3[2][4][4];
    #pragma unroll
    for (int mt = 0; mt < 2; mt++)
        #pragma unroll
        for (int nt = 0; nt < 4; nt++)
            #pragma unroll
            for (int q = 0; q < 4; q++) { S1[mt][nt][q]=0.f; S2[mt][nt][q]=0.f; S3[mt][nt][q]=0.f; }

    // per-thread ldmatrix row offsets
    const uint32_t aRowOff = (lane & 15) * 80 + (lane >> 4) * 16;
    const uint32_t bRowOff = (((lane >> 4) & 1) * 8 + (lane & 7)) * 80 + ((lane >> 3) & 1) * 16;
    const int m0 = (wid & 3) * 32;    // 4 m-warps
    const int n0 = (wid >> 2) * 32;   // 2 n-warps
    const uint32_t amBase = (uint32_t)m0 * 80 + aRowOff;
    const uint32_t bnBase = (uint32_t)n0 * 80 + bRowOff;

    for (int s = 0; s < NSTAGE; s++) {
        const int cur = s & 1;
        const uint32_t aBuf = sb + cur * STG_BYTES;
        const uint32_t bBuf = sb + B_OFF + cur * BS_BUF;

        // ---- generate phase B tiles for stage s (each warp: 8 points, lane = g) ----
        {
            int gl = lane;
            int g  = s * KC + gl;
            int i1 = g / 400;
            int i2 = (g / 20) % 20;
            int i3 = g % 20;
            #pragma unroll
            for (int pi = 0; pi < 8; pi++) {
                int p = wid * 8 + pi;
                float2 e1 = se[(0 * NTILE + p) * NGR + i1];
                float2 e2 = se[(1 * NTILE + p) * NGR + i2];
                float2 e3 = se[(2 * NTILE + p) * NGR + i3];
                float2 ph = cmul(cmul(e1, e2), e3);
                float pr = ph.x, pim = ph.y, ps = pr + pim;
                __nv_bfloat16 prh = __float2bfloat16(pr);
                __nv_bfloat16 prl = __float2bfloat16(pr - __bfloat162float(prh));
                __nv_bfloat16 pih = __float2bfloat16(pim);
                __nv_bfloat16 pil = __float2bfloat16(pim - __bfloat162float(pih));
                __nv_bfloat16 psh = __float2bfloat16(ps);
                __nv_bfloat16 psl = __float2bfloat16(ps - __bfloat162float(psh));
                uint32_t off = (uint32_t)p * 80 + gl * 2;
                char* bptr = smem + B_OFF + cur * BS_BUF;
                *(__nv_bfloat16*)(bptr + 0 * BS_VAR + off) = prh;
                *(__nv_bfloat16*)(bptr + 1 * BS_VAR + off) = prl;
                *(__nv_bfloat16*)(bptr + 2 * BS_VAR + off) = pih;
                *(__nv_bfloat16*)(bptr + 3 * BS_VAR + off) = pil;
                *(__nv_bfloat16*)(bptr + 4 * BS_VAR + off) = psh;
                *(__nv_bfloat16*)(bptr + 5 * BS_VAR + off) = psl;
            }
        }
        __syncthreads();   // B(s) visible; all MMA(s-1) complete -> A buf (s+1)&1 free

        // ---- issue bulk copy for stage s+1 into the other A buffer ----
        if (tid == 0 && s + 1 < NSTAGE) {
            uint32_t nb = (s + 1) & 1;
            uint32_t mb = nb ? mbar1 : mbar0;
            asm volatile("mbarrier.arrive.expect_tx.shared.b64 _, [%0], %1;"
                         :: "r"(mb), "r"((uint32_t)STG_BYTES) : "memory");
            const char* src = (const char*)d_A2 + (size_t)(s + 1) * STG_BYTES;
            asm volatile("cp.async.bulk.shared::cluster.global.mbarrier::complete_tx::bytes [%0], [%1], %2, [%3];"
                         :: "r"(sb + nb * STG_BYTES), "l"(src), "r"((uint32_t)STG_BYTES), "r"(mb) : "memory");
        }

        // ---- wait for A(s), then mma ----
        MBAR_WAIT(cur ? mbar1 : mbar0, (uint32_t)((s >> 1) & 1));

        #pragma unroll
        for (int k16 = 0; k16 < 2; k16++) {
            uint32_t kb = k16 * 32;
            mma_set(S1, aBuf + 0*AS_VAR + amBase + kb, aBuf + 1*AS_VAR + amBase + kb,
                        bBuf + 0*BS_VAR + bnBase + kb, bBuf + 1*BS_VAR + bnBase + kb);
            mma_set(S2, aBuf + 2*AS_VAR + amBase + kb, aBuf + 3*AS_VAR + amBase + kb,
                        bBuf + 2*BS_VAR + bnBase + kb, bBuf + 3*BS_VAR + bnBase + kb);
            mma_set(S3, aBuf + 4*AS_VAR + amBase + kb, aBuf + 5*AS_VAR + amBase + kb,
                        bBuf + 4*BS_VAR + bnBase + kb, bBuf + 5*BS_VAR + bnBase + kb);
        }
    }

    // ---- epilogue: Re = S1-S2, Im = S3-S1-S2; rotate by k, scale, store ----
    const bool cplx = (out_elems >= 2 * NB * NPTS);
    const float scale = d_scale;
    #pragma unroll
    for (int mt = 0; mt < 2; mt++) {
        #pragma unroll
        for (int nt = 0; nt < 4; nt++) {
            #pragma unroll
            for (int q = 0; q < 4; q++) {
                float v1 = S1[mt][nt][q], v2 = S2[mt][nt][q], v3 = S3[mt][nt][q];
                float Re = v1 - v2;
                float Im = v3 - v1 - v2;
                int b = m0 + mt * 16 + (lane >> 2) + (q >> 1) * 8;
                int p = p0 + n0 + nt * 8 + (lane & 3) * 2 + (q & 1);
                int kq = (b >> 4) & 3;
                const float* rp = r + p * 3;
                float ang = kg[3*kq]*rp[0] + kg[3*kq+1]*rp[1] + kg[3*kq+2]*rp[2];
                float sv, cv;
                sincosf(ang, &sv, &cv);
                float ore = (Re * cv - Im * sv) * scale;
                float oim = (Re * sv + Im * cv) * scale;
                size_t idx = (size_t)b * NPTS + p;
                if (cplx) ((float2*)out)[idx] = make_float2(ore, oim);
                else      out[idx] = ore;
            }
        }
    }
}

extern "C" void kernel_launch(void* const* d_in, const int* in_sizes, int n_in,
                              void* d_out, int out_size) {
    const float* A   = nullptr;
    const float* kg  = nullptr;
    const float* r   = nullptr;
    const float* cre = nullptr;
    const float* cim = nullptr;
    for (int i = 0; i < n_in; i++) {
        const float* p = (const float*)d_in[i];
        long long sz = in_sizes[i];
        if (sz == 9 || sz == 36)               A = p;
        else if (sz == 12 || sz == 48)         kg = p;
        else if (sz == 24000 || sz == 96000)   r = p;
        else if (sz == (long long)NB * NG || sz == (long long)NB * NG * 4) {
            if (!cre) cre = p; else cim = p;
        }
    }
    if (!A || !kg || !r || !cre || !cim) {
        if (n_in >= 5) {
            A   = (const float*)d_in[0];
            kg  = (const float*)d_in[1];
            cre = (const float*)d_in[2];
            cim = (const float*)d_in[3];
            r   = (const float*)d_in[4];
        } else {
            return;
        }
    }

    static bool attr_set = false;
    if (!attr_set) {
        cudaFuncSetAttribute(mma_kernel, cudaFuncAttributeMaxDynamicSharedMemorySize, SM_TOTAL);
        attr_set = true;
    }

    prep_kernel<<<NB, 256>>>(cre, cim, A);
    mma_kernel<<<NCTA, NT, SM_TOTAL>>>(r, kg, (float*)d_out, out_size);
}